// round 11
// baseline (speedup 1.0000x reference)
#include <cuda_runtime.h>
#include <cstdint>
#include <math.h>

// Attention_89627377533069 — FA2, tf32 mma.sync, 2 CTAs/SM.
// memory [8,1024,2048] f32 (K|V), query [8,1024,1024] f32, seq_mask [8,1024] i32, b [1] f32
// out [8,1024,1024] f32. Scalar bias b is softmax-shift-invariant -> ignored (exact).
//
// P stays in registers: PV uses a permuted Vt column layout so the sacc register
// layout (keys {2c,2c+1}) is directly a valid A-fragment (keys {c,c+4} remapped).

#define B_      8
#define S_      1024
#define H_      8
#define D_      128
#define UNITS_  1024
#define BM      64           // query rows per CTA
#define BN      32           // keys per tile
#define NWARP   4
#define NTHREAD 128
#define NITER   (S_ / BN)    // 32
#define KPAD    132          // K / V staging row pitch (floats); 528B, 528%128=16 -> LDSM ok
#define VTPAD   36           // Vt row pitch (floats); 144B, 144%128=16 -> LDSM ok

// smem float offsets
#define K_OFF(s)  ((s) * (BN * KPAD))                 // 0, 4224
#define V_OFF(s)  (2 * BN * KPAD + (s) * (BN * KPAD)) // 8448, 12672
#define M_OFF(s)  (4 * BN * KPAD + (s) * BN)          // 16896, 16928
#define VT_OFF    (4 * BN * KPAD + 2 * BN)            // 16960 (Vt: 128 x VTPAD)
#define SMEM_FLOATS (VT_OFF + D_ * VTPAD)             // 21568
#define SMEM_BYTES  (SMEM_FLOATS * 4)                 // 86272  -> 2 CTAs/SM

__device__ __forceinline__ uint32_t f2tf(float x) {
    uint32_t u;
    asm("cvt.rna.tf32.f32 %0, %1;" : "=r"(u) : "f"(x));
    return u;
}
__device__ __forceinline__ float f2tff(float x) { return __uint_as_float(f2tf(x)); }

__device__ __forceinline__ void mma8(float* c, const uint32_t* a, uint32_t b0, uint32_t b1) {
    asm volatile(
        "mma.sync.aligned.m16n8k8.row.col.f32.tf32.tf32.f32 "
        "{%0,%1,%2,%3}, {%4,%5,%6,%7}, {%8,%9}, {%0,%1,%2,%3};\n"
        : "+f"(c[0]), "+f"(c[1]), "+f"(c[2]), "+f"(c[3])
        : "r"(a[0]), "r"(a[1]), "r"(a[2]), "r"(a[3]), "r"(b0), "r"(b1));
}

// fp32-via-b16 ldmatrix: lane i receives fp32 element (row=i/4, col=i%4) of each
// 8x4 fp32 block == tf32 mma fragment layout.
__device__ __forceinline__ void ldsm4(uint32_t& r0, uint32_t& r1, uint32_t& r2, uint32_t& r3,
                                      uint32_t addr) {
    asm volatile("ldmatrix.sync.aligned.m8n8.x4.shared.b16 {%0,%1,%2,%3}, [%4];\n"
                 : "=r"(r0), "=r"(r1), "=r"(r2), "=r"(r3)
                 : "r"(addr)
                 : "memory");
}

__device__ __forceinline__ void cp16(uint32_t s, const void* g) {
    asm volatile("cp.async.ca.shared.global [%0], [%1], 16;\n" :: "r"(s), "l"(g));
}
__device__ __forceinline__ void cp4(uint32_t s, const void* g) {
    asm volatile("cp.async.ca.shared.global [%0], [%1], 4;\n" :: "r"(s), "l"(g));
}

__global__ void __launch_bounds__(NTHREAD, 2)
attn_fa2_tf32_kernel(const float* __restrict__ memory,
                     const float* __restrict__ query,
                     const int*   __restrict__ seq_mask,
                     float*       __restrict__ out)
{
    extern __shared__ float sm[];
    const int tid  = threadIdx.x;
    const int warp = tid >> 5;
    const int lane = tid & 31;
    const int r = lane >> 2;    // fragment row group
    const int c = lane & 3;     // thread-in-group
    const int qtile = blockIdx.x;
    const int batch = blockIdx.y >> 3;
    const int head  = blockIdx.y & 7;

    const float* Kg = memory + (size_t)batch * S_ * 2048 + head * D_;
    const float* Vg = Kg + UNITS_;
    const int*   Mg = seq_mask + batch * S_;

    const uint32_t smbase = (uint32_t)__cvta_generic_to_shared(sm);

    // ---- per-lane LDSM address components ----
    // K B-frags (K tile [key][d]): per 16-key pair, lanes 0-7: rows 0-7 col-lo,
    // 8-15: rows 0-7 col-hi, 16-23: rows 8-15 col-lo, 24-31: rows 8-15 col-hi.
    const int kg = lane >> 3;
    const int kRow = ((kg >> 1) << 3) + (lane & 7);
    const int kCol = (kg & 1) << 2;
    const uint32_t kLaneOff = (uint32_t)(kRow * KPAD + kCol) * 4u;

    // Vt B-frags (Vt [d][key], key columns slot-permuted): m0/m1 = (b0,b1) of
    // d-tile 2tp, m2/m3 = (b0,b1) of d-tile 2tp+1.
    const int vRow = (((lane >> 4) & 1) << 3) + (lane & 7);
    const int vCol = ((lane >> 3) & 1) << 2;
    const uint32_t vtBase = smbase + (uint32_t)(VT_OFF + vRow * VTPAD + vCol) * 4u;

    // ---- Q fragments in registers (pre-scaled, rna tf32) ----
    uint32_t qa[16][4];
    {
        const float* Qp = query + ((size_t)batch * S_ + (size_t)qtile * BM + warp * 16) * UNITS_
                        + head * D_;
        const float scale = 0.08838834764831845f;  // 1/sqrt(128)
        #pragma unroll
        for (int kc = 0; kc < 16; kc++) {
            qa[kc][0] = f2tf(Qp[(size_t)r * UNITS_ + kc * 8 + c] * scale);
            qa[kc][1] = f2tf(Qp[(size_t)(r + 8) * UNITS_ + kc * 8 + c] * scale);
            qa[kc][2] = f2tf(Qp[(size_t)r * UNITS_ + kc * 8 + c + 4] * scale);
            qa[kc][3] = f2tf(Qp[(size_t)(r + 8) * UNITS_ + kc * 8 + c + 4] * scale);
        }
    }

    float oacc[16][4];
    #pragma unroll
    for (int t = 0; t < 16; t++) {
        oacc[t][0] = 0.f; oacc[t][1] = 0.f; oacc[t][2] = 0.f; oacc[t][3] = 0.f;
    }
    float m0 = -INFINITY, m1 = -INFINITY;
    float l0 = 0.f, l1 = 0.f;

    // ---- double-buffered KV tile loader ----
    auto issue = [&](int stage, int kt) {
        const int kb = kt * BN;
        #pragma unroll
        for (int i = 0; i < 8; i++) {
            int idx = tid + i * NTHREAD;            // 0..1023
            int row = idx >> 5;                      // 0..31
            int c4  = (idx & 31) * 4;                // 0..124 floats
            cp16(smbase + (uint32_t)(K_OFF(stage) + row * KPAD + c4) * 4,
                 Kg + (size_t)(kb + row) * 2048 + c4);
            cp16(smbase + (uint32_t)(V_OFF(stage) + row * KPAD + c4) * 4,
                 Vg + (size_t)(kb + row) * 2048 + c4);
        }
        if (tid < BN)
            cp4(smbase + (uint32_t)(M_OFF(stage) + tid) * 4, Mg + kb + tid);
        asm volatile("cp.async.commit_group;\n" ::: "memory");
    };

    issue(0, 0);

    for (int kt = 0; kt < NITER; kt++) {
        const int cur = kt & 1;

        asm volatile("cp.async.wait_group 0;\n" ::: "memory");
        __syncthreads();   // tile visible; all warps past previous compute (WAR on Vt/K)

        if (kt + 1 < NITER) issue(cur ^ 1, kt + 1);   // overlaps prep + compute

        // ---- prep: K cvt-in-place; V transpose + cvt into slot-permuted Vt ----
        {
            float* Kc = sm + K_OFF(cur);
            #pragma unroll
            for (int i = 0; i < 8; i++) {
                int lin = tid + i * NTHREAD;
                int row = lin >> 5, c4 = (lin & 31) * 4;
                float4* p = (float4*)(Kc + row * KPAD + c4);
                float4 v = *p;
                v.x = f2tff(v.x); v.y = f2tff(v.y); v.z = f2tff(v.z); v.w = f2tff(v.w);
                *p = v;
            }
            const float* Vc = sm + V_OFF(cur);
            float* Vt = sm + VT_OFF;
            #pragma unroll
            for (int i = 0; i < 8; i++) {
                int lin = tid + i * NTHREAD;
                int key = lin & 31;                  // = lane -> conflict-free
                int d4  = (lin >> 5) * 4;            // 0..124
                // slot permutation within each 8-key group:
                // column m holds key slot 2m (m<4) / 2(m-4)+1 (m>=4)
                int s7 = key & 7;
                int col = (key & ~7) + (s7 >> 1) + ((s7 & 1) << 2);
                float4 v = *(const float4*)(Vc + key * KPAD + d4);
                Vt[(d4 + 0) * VTPAD + col] = f2tff(v.x);
                Vt[(d4 + 1) * VTPAD + col] = f2tff(v.y);
                Vt[(d4 + 2) * VTPAD + col] = f2tff(v.z);
                Vt[(d4 + 3) * VTPAD + col] = f2tff(v.w);
            }
        }
        __syncthreads();   // prep visible

        const int* Ms = (const int*)(sm + M_OFF(cur));
        const uint32_t kStageBase = smbase + (uint32_t)K_OFF(cur) * 4u + kLaneOff;

        // ---- S = Q K^T  ([16 x 32] per warp); K already tf32 ----
        float sacc[4][4];
        #pragma unroll
        for (int j = 0; j < 4; j++) {
            sacc[j][0] = 0.f; sacc[j][1] = 0.f; sacc[j][2] = 0.f; sacc[j][3] = 0.f;
        }
        #pragma unroll
        for (int kc = 0; kc < 16; kc++) {
            #pragma unroll
            for (int p = 0; p < 2; p++) {
                uint32_t b0, b1, b2, b3;
                ldsm4(b0, b1, b2, b3,
                      kStageBase + (uint32_t)(p * 16 * KPAD + kc * 8) * 4u);
                mma8(sacc[2 * p],     qa[kc], b0, b1);
                mma8(sacc[2 * p + 1], qa[kc], b2, b3);
            }
        }

        // ---- key mask (additive -1e30) ----
        #pragma unroll
        for (int j = 0; j < 4; j++) {
            float a0 = Ms[j * 8 + 2 * c]     ? 0.f : -1e30f;
            float a1 = Ms[j * 8 + 2 * c + 1] ? 0.f : -1e30f;
            sacc[j][0] += a0; sacc[j][2] += a0;
            sacc[j][1] += a1; sacc[j][3] += a1;
        }

        // ---- online softmax (rows owned by warp; quad shuffles only) ----
        float mx0 = -INFINITY, mx1 = -INFINITY;
        #pragma unroll
        for (int j = 0; j < 4; j++) {
            mx0 = fmaxf(mx0, fmaxf(sacc[j][0], sacc[j][1]));
            mx1 = fmaxf(mx1, fmaxf(sacc[j][2], sacc[j][3]));
        }
        mx0 = fmaxf(mx0, __shfl_xor_sync(0xffffffffu, mx0, 1));
        mx0 = fmaxf(mx0, __shfl_xor_sync(0xffffffffu, mx0, 2));
        mx1 = fmaxf(mx1, __shfl_xor_sync(0xffffffffu, mx1, 1));
        mx1 = fmaxf(mx1, __shfl_xor_sync(0xffffffffu, mx1, 2));

        float mn0 = fmaxf(m0, mx0), mn1 = fmaxf(m1, mx1);
        float al0 = __expf(m0 - mn0), al1 = __expf(m1 - mn1);
        m0 = mn0; m1 = mn1;

        // P in registers, tf32-rounded; layout already a valid PV A-fragment
        // (keys {2c,2c+1} remapped onto mma-k {c,c+4} via the Vt column permute).
        uint32_t pa[4][4];
        float rs0 = 0.f, rs1 = 0.f;
        #pragma unroll
        for (int j = 0; j < 4; j++) {
            float p0 = f2tff(__expf(sacc[j][0] - mn0));  // (r,   2c)
            float p1 = f2tff(__expf(sacc[j][1] - mn0));  // (r,   2c+1)
            float p2 = f2tff(__expf(sacc[j][2] - mn1));  // (r+8, 2c)
            float p3 = f2tff(__expf(sacc[j][3] - mn1));  // (r+8, 2c+1)
            rs0 += p0 + p1;
            rs1 += p2 + p3;
            pa[j][0] = __float_as_uint(p0);   // A(k=c)
            pa[j][1] = __float_as_uint(p2);
            pa[j][2] = __float_as_uint(p1);   // A(k=c+4)
            pa[j][3] = __float_as_uint(p3);
        }
        rs0 += __shfl_xor_sync(0xffffffffu, rs0, 1);
        rs0 += __shfl_xor_sync(0xffffffffu, rs0, 2);
        rs1 += __shfl_xor_sync(0xffffffffu, rs1, 1);
        rs1 += __shfl_xor_sync(0xffffffffu, rs1, 2);
        l0 = l0 * al0 + rs0;
        l1 = l1 * al1 + rs1;

        #pragma unroll
        for (int t = 0; t < 16; t++) {
            oacc[t][0] *= al0; oacc[t][1] *= al0;
            oacc[t][2] *= al1; oacc[t][3] *= al1;
        }

        // ---- O += P V  (A from registers, B via LDSM from permuted Vt) ----
        #pragma unroll
        for (int kc = 0; kc < 4; kc++) {
            #pragma unroll
            for (int tp = 0; tp < 8; tp++) {
                uint32_t v0, v1, v2, v3;
                ldsm4(v0, v1, v2, v3, vtBase + (uint32_t)(tp * 16 * VTPAD + kc * 8) * 4u);
                mma8(oacc[2 * tp],     pa[kc], v0, v1);
                mma8(oacc[2 * tp + 1], pa[kc], v2, v3);
            }
        }
        // next iteration's top __syncthreads guards Vt/K reuse
    }

    // ---- epilogue: normalize + store ----
    const float li0 = 1.f / l0;
    const float li1 = 1.f / l1;
    float* Op = out + ((size_t)batch * S_ + (size_t)qtile * BM + warp * 16) * UNITS_ + head * D_;
    #pragma unroll
    for (int t = 0; t < 16; t++) {
        *(float2*)(Op + (size_t)r * UNITS_ + t * 8 + 2 * c) =
            make_float2(oacc[t][0] * li0, oacc[t][1] * li0);
        *(float2*)(Op + (size_t)(r + 8) * UNITS_ + t * 8 + 2 * c) =
            make_float2(oacc[t][2] * li1, oacc[t][3] * li1);
    }
}

extern "C" void kernel_launch(void* const* d_in, const int* in_sizes, int n_in,
                              void* d_out, int out_size)
{
    const float* memory = (const float*)d_in[0];
    const float* query  = (const float*)d_in[1];
    const int*   seqm   = (const int*)d_in[2];
    // d_in[3] (scalar bias b) is provably a no-op under softmax -> ignored.

    cudaFuncSetAttribute(attn_fa2_tf32_kernel,
                         cudaFuncAttributeMaxDynamicSharedMemorySize, SMEM_BYTES);

    dim3 grid(S_ / BM, B_ * H_);
    attn_fa2_tf32_kernel<<<grid, NTHREAD, SMEM_BYTES>>>(memory, query, seqm, (float*)d_out);
}

// round 13
// speedup vs baseline: 2.2778x; 2.2778x over previous
#include <cuda_runtime.h>
#include <cuda_fp16.h>
#include <cstdint>
#include <math.h>

// Attention_89627377533069 — FA2, fp16 mma.m16n8k16, f32 accum.
// memory [8,1024,2048] f32 (K|V), query [8,1024,1024] f32, seq_mask [8,1024] i32, b [1] f32
// out [8,1024,1024] f32. Scalar bias b is softmax-shift-invariant -> ignored (exact).
//
// Kernel 1 converts inputs once to fp16 (RNE) into __device__ scratch, head-major.
// Kernel 2 is the attention: K via ldmatrix, V via ldmatrix.trans, P stays in regs.

#define B_      8
#define S_      1024
#define H_      8
#define D_      128
#define UNITS_  1024
#define BM      64
#define BN      64
#define NTHREAD 128
#define NITER   (S_ / BN)    // 16

// fp16 scratch, head-major [b*8+h][s][d]
__device__ __half g_Qh[B_ * H_ * S_ * D_];
__device__ __half g_Kh[B_ * H_ * S_ * D_];
__device__ __half g_Vh[B_ * H_ * S_ * D_];

// smem: K/V tiles [64 rows][136 halfs] (272B pitch; 272%128=16 -> conflict-free ldmatrix)
#define KPITCH_H  136
#define KPITCH_B  272
#define TILE_B    (BN * KPITCH_B)          // 17408
#define KOFFB(s)  ((uint32_t)(s) * TILE_B)            // 0, 17408
#define VOFFB(s)  (uint32_t)(2 * TILE_B + (s) * TILE_B) // 34816, 52224
#define MOFFB(s)  (uint32_t)(4 * TILE_B + (s) * 256)    // 69632, 69888
#define SMEM_BYTES (4 * TILE_B + 512)      // 70144 -> 2 CTAs/SM

__device__ __forceinline__ uint32_t h2u(__half2 h) {
    union { __half2 h; uint32_t u; } cvt;
    cvt.h = h;
    return cvt.u;
}

__device__ __forceinline__ void mma16(float* c, const uint32_t* a, uint32_t b0, uint32_t b1) {
    asm volatile(
        "mma.sync.aligned.m16n8k16.row.col.f32.f16.f16.f32 "
        "{%0,%1,%2,%3}, {%4,%5,%6,%7}, {%8,%9}, {%0,%1,%2,%3};\n"
        : "+f"(c[0]), "+f"(c[1]), "+f"(c[2]), "+f"(c[3])
        : "r"(a[0]), "r"(a[1]), "r"(a[2]), "r"(a[3]), "r"(b0), "r"(b1));
}

__device__ __forceinline__ void ldsm4(uint32_t& r0, uint32_t& r1, uint32_t& r2, uint32_t& r3,
                                      uint32_t addr) {
    asm volatile("ldmatrix.sync.aligned.m8n8.x4.shared.b16 {%0,%1,%2,%3}, [%4];\n"
                 : "=r"(r0), "=r"(r1), "=r"(r2), "=r"(r3) : "r"(addr) : "memory");
}
__device__ __forceinline__ void ldsm4t(uint32_t& r0, uint32_t& r1, uint32_t& r2, uint32_t& r3,
                                       uint32_t addr) {
    asm volatile("ldmatrix.sync.aligned.m8n8.x4.trans.shared.b16 {%0,%1,%2,%3}, [%4];\n"
                 : "=r"(r0), "=r"(r1), "=r"(r2), "=r"(r3) : "r"(addr) : "memory");
}

__device__ __forceinline__ void cp16(uint32_t s, const void* g) {
    asm volatile("cp.async.ca.shared.global [%0], [%1], 16;\n" :: "r"(s), "l"(g));
}
__device__ __forceinline__ void cp4(uint32_t s, const void* g) {
    asm volatile("cp.async.ca.shared.global [%0], [%1], 4;\n" :: "r"(s), "l"(g));
}

// ---------------- convert kernel: f32 -> fp16 scratch (head-major) ----------------
__global__ void __launch_bounds__(256, 4)
convert_kernel(const float* __restrict__ memory, const float* __restrict__ query)
{
    const int idx = blockIdx.x * 256 + threadIdx.x;   // 0 .. 1048575
    const int d0 = (idx & 15) * 8;
    const int s  = (idx >> 4) & 1023;
    const int h  = (idx >> 14) & 7;
    const int b  = idx >> 17;
    const float scale = 0.08838834764831845f;  // 1/sqrt(128)

    const size_t dst = (((size_t)(b * 8 + h) * S_) + s) * D_ + d0;
    const float* qp = query  + ((size_t)b * S_ + s) * UNITS_ + h * D_ + d0;
    const float* kp = memory + ((size_t)b * S_ + s) * 2048   + h * D_ + d0;
    const float* vp = kp + UNITS_;

    float4 a0 = ((const float4*)qp)[0], a1 = ((const float4*)qp)[1];
    uint4 q;
    q.x = h2u(__floats2half2_rn(a0.x * scale, a0.y * scale));
    q.y = h2u(__floats2half2_rn(a0.z * scale, a0.w * scale));
    q.z = h2u(__floats2half2_rn(a1.x * scale, a1.y * scale));
    q.w = h2u(__floats2half2_rn(a1.z * scale, a1.w * scale));
    *(uint4*)(g_Qh + dst) = q;

    a0 = ((const float4*)kp)[0]; a1 = ((const float4*)kp)[1];
    q.x = h2u(__floats2half2_rn(a0.x, a0.y));
    q.y = h2u(__floats2half2_rn(a0.z, a0.w));
    q.z = h2u(__floats2half2_rn(a1.x, a1.y));
    q.w = h2u(__floats2half2_rn(a1.z, a1.w));
    *(uint4*)(g_Kh + dst) = q;

    a0 = ((const float4*)vp)[0]; a1 = ((const float4*)vp)[1];
    q.x = h2u(__floats2half2_rn(a0.x, a0.y));
    q.y = h2u(__floats2half2_rn(a0.z, a0.w));
    q.z = h2u(__floats2half2_rn(a1.x, a1.y));
    q.w = h2u(__floats2half2_rn(a1.z, a1.w));
    *(uint4*)(g_Vh + dst) = q;
}

// ---------------- attention kernel ----------------
__global__ void __launch_bounds__(NTHREAD, 2)
attn_fa2_fp16_kernel(const int* __restrict__ seq_mask, float* __restrict__ out)
{
    extern __shared__ char smem[];
    const int tid  = threadIdx.x;
    const int warp = tid >> 5;
    const int lane = tid & 31;
    const int r = lane >> 2;    // fragment row group
    const int c = lane & 3;     // thread-in-group
    const int qtile = blockIdx.x;
    const int bh    = blockIdx.y;           // b*8 + h
    const int batch = bh >> 3;

    const __half* Kh = g_Kh + (size_t)bh * S_ * D_;
    const __half* Vh = g_Vh + (size_t)bh * S_ * D_;
    const int*    Mg = seq_mask + batch * S_;

    const uint32_t smb = (uint32_t)__cvta_generic_to_shared(smem);

    // ---- ldmatrix per-lane address components ----
    // K (non-trans): matrices (m0,m1)=(keys 0-7, d 0/8), (m2,m3)=(keys 8-15, d 0/8)
    const int kRow = (lane & 7) + ((lane >> 4) << 3);        // key 0..15
    const int kColH = ((lane >> 3) & 1) << 3;                // d 0 or 8 (halfs)
    const uint32_t kLaneOff = (uint32_t)(kRow * KPITCH_B + kColH * 2);
    // V (trans): matrices (m0,m1)=(keys 0-7/8-15, d 0), (m2,m3)=(keys 0-7/8-15, d 8)
    const int vRow = (lane & 7) + (((lane >> 3) & 1) << 3);  // key 0..15
    const int vColH = (lane >> 4) << 3;                      // d 0 or 8 (halfs)
    const uint32_t vLaneOff = (uint32_t)(vRow * KPITCH_B + vColH * 2);

    // ---- Q A-fragments in registers (pre-scaled fp16 from scratch) ----
    uint32_t qa[8][4];
    {
        const __half* Qp = g_Qh + ((size_t)bh * S_ + qtile * BM + warp * 16) * D_;
        #pragma unroll
        for (int kc = 0; kc < 8; kc++) {
            qa[kc][0] = *(const uint32_t*)(Qp + (size_t)r * D_       + kc * 16 + 2 * c);
            qa[kc][1] = *(const uint32_t*)(Qp + (size_t)(r + 8) * D_ + kc * 16 + 2 * c);
            qa[kc][2] = *(const uint32_t*)(Qp + (size_t)r * D_       + kc * 16 + 2 * c + 8);
            qa[kc][3] = *(const uint32_t*)(Qp + (size_t)(r + 8) * D_ + kc * 16 + 2 * c + 8);
        }
    }

    float oacc[16][4];
    #pragma unroll
    for (int t = 0; t < 16; t++) {
        oacc[t][0] = 0.f; oacc[t][1] = 0.f; oacc[t][2] = 0.f; oacc[t][3] = 0.f;
    }
    float m0 = -INFINITY, m1 = -INFINITY;
    float l0 = 0.f, l1 = 0.f;

    // ---- double-buffered KV tile loader (fp16, 256B rows) ----
    auto issue = [&](int stage, int kt) {
        const __half* Ks = Kh + (size_t)(kt * BN) * D_;
        const __half* Vs = Vh + (size_t)(kt * BN) * D_;
        #pragma unroll
        for (int i = 0; i < 8; i++) {
            int lin = tid + i * NTHREAD;          // 0..1023
            int row = lin >> 4;                    // 0..63
            int ch  = (lin & 15) * 16;             // byte 0..240
            cp16(smb + KOFFB(stage) + (uint32_t)(row * KPITCH_B + ch),
                 (const char*)(Ks + (size_t)row * D_) + ch);
            cp16(smb + VOFFB(stage) + (uint32_t)(row * KPITCH_B + ch),
                 (const char*)(Vs + (size_t)row * D_) + ch);
        }
        if (tid < BN)
            cp4(smb + MOFFB(stage) + tid * 4, Mg + kt * BN + tid);
        asm volatile("cp.async.commit_group;\n" ::: "memory");
    };

    issue(0, 0);

    for (int kt = 0; kt < NITER; kt++) {
        const int cur = kt & 1;

        asm volatile("cp.async.wait_group 0;\n" ::: "memory");
        __syncthreads();   // tile ready; all warps past previous iter (WAR on other stage)

        if (kt + 1 < NITER) issue(cur ^ 1, kt + 1);

        const int* Ms = (const int*)(smem + MOFFB(cur));
        const uint32_t kBase = smb + KOFFB(cur) + kLaneOff;
        const uint32_t vBase = smb + VOFFB(cur) + vLaneOff;

        // ---- S = Q K^T  ([16q x 64k] per warp) ----
        float sacc[8][4];
        #pragma unroll
        for (int j = 0; j < 8; j++) {
            sacc[j][0] = 0.f; sacc[j][1] = 0.f; sacc[j][2] = 0.f; sacc[j][3] = 0.f;
        }
        #pragma unroll
        for (int kc = 0; kc < 8; kc++) {          // d chunks of 16
            #pragma unroll
            for (int p = 0; p < 4; p++) {          // key groups of 16
                uint32_t b0, b1, b2, b3;
                ldsm4(b0, b1, b2, b3,
                      kBase + (uint32_t)(p * 16 * KPITCH_B + kc * 32));
                mma16(sacc[2 * p],     qa[kc], b0, b1);
                mma16(sacc[2 * p + 1], qa[kc], b2, b3);
            }
        }

        // ---- key mask (additive -1e30) ----
        #pragma unroll
        for (int j = 0; j < 8; j++) {
            float a0 = Ms[j * 8 + 2 * c]     ? 0.f : -1e30f;
            float a1 = Ms[j * 8 + 2 * c + 1] ? 0.f : -1e30f;
            sacc[j][0] += a0; sacc[j][2] += a0;
            sacc[j][1] += a1; sacc[j][3] += a1;
        }

        // ---- online softmax ----
        float mx0 = -INFINITY, mx1 = -INFINITY;
        #pragma unroll
        for (int j = 0; j < 8; j++) {
            mx0 = fmaxf(mx0, fmaxf(sacc[j][0], sacc[j][1]));
            mx1 = fmaxf(mx1, fmaxf(sacc[j][2], sacc[j][3]));
        }
        mx0 = fmaxf(mx0, __shfl_xor_sync(0xffffffffu, mx0, 1));
        mx0 = fmaxf(mx0, __shfl_xor_sync(0xffffffffu, mx0, 2));
        mx1 = fmaxf(mx1, __shfl_xor_sync(0xffffffffu, mx1, 1));
        mx1 = fmaxf(mx1, __shfl_xor_sync(0xffffffffu, mx1, 2));

        float mn0 = fmaxf(m0, mx0), mn1 = fmaxf(m1, mx1);
        float al0 = __expf(m0 - mn0), al1 = __expf(m1 - mn1);
        m0 = mn0; m1 = mn1;

        // ---- P -> fp16 A-fragments directly in registers ----
        // A chunk kc (16 keys): a0=(r, k=2c,2c+1); a1=(r+8, same); a2/a3 = +8 keys.
        uint32_t pa[4][4];
        float rs0 = 0.f, rs1 = 0.f;
        #pragma unroll
        for (int j = 0; j < 8; j++) {
            __half2 h01 = __floats2half2_rn(__expf(sacc[j][0] - mn0), __expf(sacc[j][1] - mn0));
            __half2 h23 = __floats2half2_rn(__expf(sacc[j][2] - mn1), __expf(sacc[j][3] - mn1));
            float2 f01 = __half22float2(h01);
            float2 f23 = __half22float2(h23);
            rs0 += f01.x + f01.y;
            rs1 += f23.x + f23.y;
            pa[j >> 1][(j & 1) ? 2 : 0] = h2u(h01);
            pa[j >> 1][(j & 1) ? 3 : 1] = h2u(h23);
        }
        rs0 += __shfl_xor_sync(0xffffffffu, rs0, 1);
        rs0 += __shfl_xor_sync(0xffffffffu, rs0, 2);
        rs1 += __shfl_xor_sync(0xffffffffu, rs1, 1);
        rs1 += __shfl_xor_sync(0xffffffffu, rs1, 2);
        l0 = l0 * al0 + rs0;
        l1 = l1 * al1 + rs1;

        #pragma unroll
        for (int t = 0; t < 16; t++) {
            oacc[t][0] *= al0; oacc[t][1] *= al0;
            oacc[t][2] *= al1; oacc[t][3] *= al1;
        }

        // ---- O += P V  (B via ldmatrix.trans on V[key][d]) ----
        #pragma unroll
        for (int kc = 0; kc < 4; kc++) {          // key chunks of 16
            #pragma unroll
            for (int dp = 0; dp < 8; dp++) {       // d pairs of 16
                uint32_t v0, v1, v2, v3;
                ldsm4t(v0, v1, v2, v3,
                       vBase + (uint32_t)(kc * 16 * KPITCH_B + dp * 32));
                mma16(oacc[2 * dp],     pa[kc], v0, v1);
                mma16(oacc[2 * dp + 1], pa[kc], v2, v3);
            }
        }
        // next iteration's top __syncthreads guards stage reuse
    }

    // ---- epilogue: normalize + store (f32) ----
    const float li0 = 1.f / l0;
    const float li1 = 1.f / l1;
    const int head = bh & 7;
    float* Op = out + ((size_t)batch * S_ + (size_t)qtile * BM + warp * 16) * UNITS_
              + head * D_;
    #pragma unroll
    for (int t = 0; t < 16; t++) {
        *(float2*)(Op + (size_t)r * UNITS_ + t * 8 + 2 * c) =
            make_float2(oacc[t][0] * li0, oacc[t][1] * li0);
        *(float2*)(Op + (size_t)(r + 8) * UNITS_ + t * 8 + 2 * c) =
            make_float2(oacc[t][2] * li1, oacc[t][3] * li1);
    }
}

extern "C" void kernel_launch(void* const* d_in, const int* in_sizes, int n_in,
                              void* d_out, int out_size)
{
    const float* memory = (const float*)d_in[0];
    const float* query  = (const float*)d_in[1];
    const int*   seqm   = (const int*)d_in[2];
    // d_in[3] (scalar bias b) is provably a no-op under softmax -> ignored.

    convert_kernel<<<4096, 256>>>(memory, query);

    cudaFuncSetAttribute(attn_fa2_fp16_kernel,
                         cudaFuncAttributeMaxDynamicSharedMemorySize, SMEM_BYTES);
    dim3 grid(S_ / BM, B_ * H_);
    attn_fa2_fp16_kernel<<<grid, NTHREAD, SMEM_BYTES>>>(seqm, (float*)d_out);
}